// round 5
// baseline (speedup 1.0000x reference)
#include <cuda_runtime.h>
#include <cstdint>

// ---------------------------------------------------------------------------
// CritiGraph: exact JAX threefry2x32 (PARTITIONABLE mode, default in modern
// JAX) reproduction + distance computation.
//
// Shapes: T=2048 rows, TP=16 coord dims, H=16 levels, K=16 masks/level,
// output (T, 2*H*K+1=513, TP) float32.
// Harness downcasts int64 inputs to int32 -> read as const int*.
// ---------------------------------------------------------------------------

#define Tn   2048
#define Hn   16
#define Kn   16
#define TPn  16
#define NCOL 513          // 2*H*K + 1

struct TFR { uint32_t a, b; };

__host__ __device__ constexpr uint32_t rotl_(uint32_t x, int d) {
    return (uint32_t)((x << d) | (x >> (32 - d)));
}

// Exact JAX threefry2x32 (20 rounds, rotations [13,15,26,6]/[17,29,16,24]).
__host__ __device__ constexpr TFR tf2x32_c(uint32_t k0, uint32_t k1,
                                           uint32_t x0, uint32_t x1) {
    uint32_t k2 = k0 ^ k1 ^ 0x1BD11BDAu;
    x0 += k0; x1 += k1;
    const int rA[4] = {13, 15, 26, 6};
    const int rB[4] = {17, 29, 16, 24};
    for (int i = 0; i < 4; i++) { x0 += x1; x1 = rotl_(x1, rA[i]); x1 ^= x0; }
    x0 += k1; x1 += k2 + 1u;
    for (int i = 0; i < 4; i++) { x0 += x1; x1 = rotl_(x1, rB[i]); x1 ^= x0; }
    x0 += k2; x1 += k0 + 2u;
    for (int i = 0; i < 4; i++) { x0 += x1; x1 = rotl_(x1, rA[i]); x1 ^= x0; }
    x0 += k0; x1 += k1 + 3u;
    for (int i = 0; i < 4; i++) { x0 += x1; x1 = rotl_(x1, rB[i]); x1 ^= x0; }
    x0 += k1; x1 += k2 + 4u;
    for (int i = 0; i < 4; i++) { x0 += x1; x1 = rotl_(x1, rA[i]); x1 ^= x0; }
    x0 += k2; x1 += k0 + 5u;
    return {x0, x1};
}

// ---- compile-time key derivation (threefry_partitionable = True) -----------
// key = jax.random.key(42) -> (0, 42)
// foldlike split: child i = tf(key, hi=0, lo=i) (both words)
constexpr TFR KM_ = tf2x32_c(0u, 42u, 0u, 0u);   // kmask = split(key)[0]
constexpr TFR KP_ = tf2x32_c(0u, 42u, 0u, 1u);   // kperm = split(key)[1]
// randint(kmask,...): k1,k2 = split(kmask); only k2 (lower_bits key) matters
// (span=2^16 divides 2^32 -> multiplier==0 -> value = lower_bits mod 2^16)
constexpr TFR KL_ = tf2x32_c(KM_.a, KM_.b, 0u, 1u);
constexpr uint32_t KLO0 = KL_.a, KLO1 = KL_.b;
// shuffle: key_, subkey = split(kperm); subkey = child 1
constexpr TFR SK_ = tf2x32_c(KP_.a, KP_.b, 0u, 1u);
constexpr uint32_t SK0 = SK_.a, SK1 = SK_.b;

// ---- fast device threefry (funnel-shift rotl) ------------------------------
__device__ __forceinline__ TFR tf2x32_d(uint32_t k0, uint32_t k1,
                                        uint32_t x0, uint32_t x1) {
    uint32_t k2 = k0 ^ k1 ^ 0x1BD11BDAu;
    x0 += k0; x1 += k1;
#define TF_R(r) { x0 += x1; x1 = __funnelshift_l(x1, x1, (r)); x1 ^= x0; }
    TF_R(13) TF_R(15) TF_R(26) TF_R(6)
    x0 += k1; x1 += k2 + 1u;
    TF_R(17) TF_R(29) TF_R(16) TF_R(24)
    x0 += k2; x1 += k0 + 2u;
    TF_R(13) TF_R(15) TF_R(26) TF_R(6)
    x0 += k0; x1 += k1 + 3u;
    TF_R(17) TF_R(29) TF_R(16) TF_R(24)
    x0 += k1; x1 += k2 + 4u;
    TF_R(13) TF_R(15) TF_R(26) TF_R(6)
    x0 += k2; x1 += k0 + 5u;
#undef TF_R
    TFR r; r.a = x0; r.b = x1; return r;
}

// inverse permutation: output column for each source column
__device__ int d_jpos[NCOL];

// ---------------------------------------------------------------------------
// Kernel A: permutation(kperm, 513), partitionable random_bits(32):
//   sort_key[i] = tf(subkey, 0, i).a ^ tf(subkey, 0, i).b
// Stable ascending sort of arange(513) by keys -> perm; jpos[i] = rank(i).
// ---------------------------------------------------------------------------
__global__ void perm_kernel() {
    __shared__ uint32_t keys[NCOL];
    int i = threadIdx.x;
    if (i < NCOL) {
        TFR o = tf2x32_d(SK0, SK1, 0u, (uint32_t)i);
        keys[i] = o.a ^ o.b;
    }
    __syncthreads();
    if (i < NCOL) {
        uint32_t ki = keys[i];
        int r = 0;
        for (int j = 0; j < NCOL; j++) {
            uint32_t kj = keys[j];
            r += (kj < ki) || (kj == ki && j < i);
        }
        d_jpos[i] = r;
    }
}

// ---------------------------------------------------------------------------
// Kernel B: main compute. Grid: T*16 blocks x 256 threads.
// Block b: t = b>>4, hk in [ (b&15)*16, +16 ), thread -> (hk, p).
// randint 64-bit partitionable: element i -> tf(KLO, 0, i); low16 = .b & 0xFFFF
// One eval serves both +result and -result columns.
// ---------------------------------------------------------------------------
__global__ __launch_bounds__(256) void main_kernel(
    const int* __restrict__ locations,
    const int* __restrict__ pos_idx,
    const float* __restrict__ norm,
    float* __restrict__ out)
{
    const int t  = blockIdx.x >> 4;
    const int hk = ((blockIdx.x & 15) << 4) + (threadIdx.x >> 4);
    const int p  = threadIdx.x & 15;

    __shared__ int   s_ori[TPn];
    __shared__ float s_norm;
    if (threadIdx.x < TPn) {
        int pi = pos_idx[t];
        s_ori[threadIdx.x] = locations[(size_t)pi * TPn + threadIdx.x];
    }
    if (threadIdx.x == 0) s_norm = norm[t];
    __syncthreads();

    const int h = hk >> 4, k = hk & 15;
    const int c2 = s_ori[p];
    int res = c2 ^ (1 << h);           // flipped; h==0 => mask is 0
    if (h) {
        uint32_t i = (uint32_t)(((h * Tn + t) * Kn + k) * TPn + p);
        TFR o = tf2x32_d(KLO0, KLO1, 0u, i);
        res ^= (int)(o.b & ((1u << h) - 1u));   // lower_bits mod 2^16, & (2^h-1)
    }

    const float nrm = s_norm;
    const int aa = (res < 0) ? -res : res;
    const int bb = (c2  < 0) ? -c2  : c2;
    const int e  = 32 - __clz((aa ^ bb) + 1);   // frexp exponent == bit length
    const float base = 1.0f - (float)e * 0.0625f;
    const bool b2 = (c2 >= 0);
    float dp = (((res >= 0) == b2) ? base : -base) * nrm;  //  result
    float dm = (((res <= 0) == b2) ? base : -base) * nrm;  // -result

    const size_t rowbase = (size_t)t * (NCOL * TPn);
    out[rowbase + (size_t)d_jpos[hk]        * TPn + p] = dp;
    out[rowbase + (size_t)d_jpos[hk + 257]  * TPn + p] = dm;

    if (hk == 0) {  // the ori column: d(ori,ori) = (1 - 1/16) * norm
        out[rowbase + (size_t)d_jpos[256] * TPn + p] = 0.9375f * nrm;
    }
}

extern "C" void kernel_launch(void* const* d_in, const int* in_sizes, int n_in,
                              void* d_out, int out_size) {
    const int*   locations = (const int*)d_in[0];
    const int*   pos_idx   = (const int*)d_in[1];
    const float* norm      = (const float*)d_in[2];
    float*       out       = (float*)d_out;

    perm_kernel<<<1, 544>>>();
    main_kernel<<<Tn * 16, 256>>>(locations, pos_idx, norm, out);
}

// round 7
// speedup vs baseline: 1.6654x; 1.6654x over previous
#include <cuda_runtime.h>
#include <cstdint>

// ---------------------------------------------------------------------------
// CritiGraph: exact JAX threefry2x32 (partitionable mode) + distance.
// T=2048, TP=16, H=16, K=16, out (T, 513, TP) fp32.
// Harness downcasts int64 inputs to int32 -> const int*.
//
// R5: - permutation computed at COMPILE TIME (constexpr radix sort) -> no
//       perm kernel, one launch.
//     - 4 hk per thread (overhead amortized, 4-way ILP).
//     - threefry adds forced to IMAD (fma pipe) via mad.lo with runtime '1'.
//     - epilogue reduced analytically: dp = +base*nrm always; dm = -dp
//       unless res==0.
// ---------------------------------------------------------------------------

#define Tn   2048
#define TPn  16
#define NCOL 513

struct TFR { uint32_t a, b; };

__host__ __device__ constexpr uint32_t rotl_(uint32_t x, int d) {
    return (uint32_t)((x << d) | (x >> (32 - d)));
}

// Exact JAX threefry2x32 (20 rounds).
__host__ __device__ constexpr TFR tf2x32_c(uint32_t k0, uint32_t k1,
                                           uint32_t x0, uint32_t x1) {
    uint32_t k2 = k0 ^ k1 ^ 0x1BD11BDAu;
    x0 += k0; x1 += k1;
    const int rA[4] = {13, 15, 26, 6};
    const int rB[4] = {17, 29, 16, 24};
    for (int i = 0; i < 4; i++) { x0 += x1; x1 = rotl_(x1, rA[i]); x1 ^= x0; }
    x0 += k1; x1 += k2 + 1u;
    for (int i = 0; i < 4; i++) { x0 += x1; x1 = rotl_(x1, rB[i]); x1 ^= x0; }
    x0 += k2; x1 += k0 + 2u;
    for (int i = 0; i < 4; i++) { x0 += x1; x1 = rotl_(x1, rA[i]); x1 ^= x0; }
    x0 += k0; x1 += k1 + 3u;
    for (int i = 0; i < 4; i++) { x0 += x1; x1 = rotl_(x1, rB[i]); x1 ^= x0; }
    x0 += k1; x1 += k2 + 4u;
    for (int i = 0; i < 4; i++) { x0 += x1; x1 = rotl_(x1, rA[i]); x1 ^= x0; }
    x0 += k2; x1 += k0 + 5u;
    return {x0, x1};
}

// ---- compile-time key derivation (threefry_partitionable = True) -----------
constexpr TFR KM_ = tf2x32_c(0u, 42u, 0u, 0u);   // kmask = split(key42)[0]
constexpr TFR KP_ = tf2x32_c(0u, 42u, 0u, 1u);   // kperm = split(key42)[1]
constexpr TFR KL_ = tf2x32_c(KM_.a, KM_.b, 0u, 1u);  // lower_bits key
constexpr uint32_t KLO0 = KL_.a, KLO1 = KL_.b;
constexpr TFR SK_ = tf2x32_c(KP_.a, KP_.b, 0u, 1u);  // shuffle subkey
constexpr uint32_t SK0 = SK_.a, SK1 = SK_.b;

// ---- compile-time inverse permutation (stable ascending radix sort) --------
// sort_key[i] = tf(subkey, 0, i).a ^ .b  (partitionable 32-bit random_bits)
struct JP { int v[NCOL]; };

constexpr JP make_jpos() {
    uint32_t keys[NCOL] = {};
    for (int i = 0; i < NCOL; i++) {
        TFR o = tf2x32_c(SK0, SK1, 0u, (uint32_t)i);
        keys[i] = o.a ^ o.b;
    }
    int idx[NCOL] = {}, tmp[NCOL] = {};
    for (int i = 0; i < NCOL; i++) idx[i] = i;
    for (int pass = 0; pass < 4; pass++) {
        int cnt[256] = {};
        for (int i = 0; i < NCOL; i++) cnt[(keys[idx[i]] >> (8 * pass)) & 255]++;
        int pos[256] = {};
        int s = 0;
        for (int b = 0; b < 256; b++) { pos[b] = s; s += cnt[b]; }
        for (int i = 0; i < NCOL; i++) {
            int b = (keys[idx[i]] >> (8 * pass)) & 255;
            tmp[pos[b]++] = idx[i];
        }
        for (int i = 0; i < NCOL; i++) idx[i] = tmp[i];
    }
    JP jp{};
    for (int r = 0; r < NCOL; r++) jp.v[idx[r]] = r;  // inverse permutation
    return jp;
}

__constant__ JP c_jp = make_jpos();

// ---- force-add-to-IMAD trick -----------------------------------------------
__device__ uint32_t g_one = 1;   // runtime 1; ptxas cannot constant-fold

__device__ __forceinline__ uint32_t madd(uint32_t a, uint32_t b, uint32_t one) {
    uint32_t r;
    asm("mad.lo.u32 %0, %1, %2, %3;" : "=r"(r) : "r"(a), "r"(one), "r"(b));
    return r;  // a*1 + b -> IMAD (fma pipe)
}

// threefry2x32, x0=0, returns second word only (x0's final injection dropped)
__device__ __forceinline__ uint32_t tf_b(uint32_t one, uint32_t ctr) {
    constexpr uint32_t k0 = KLO0, k1 = KLO1, k2 = k0 ^ k1 ^ 0x1BD11BDAu;
    uint32_t x0 = k0;
    uint32_t x1 = madd(ctr, k1, one);
#define RND(r) { x0 = madd(x1, x0, one); x1 = __funnelshift_l(x1, x1, (r)) ^ x0; }
    RND(13) RND(15) RND(26) RND(6)
    x0 = madd(x0, k1, one); x1 = madd(x1, k2 + 1u, one);
    RND(17) RND(29) RND(16) RND(24)
    x0 = madd(x0, k2, one); x1 = madd(x1, k0 + 2u, one);
    RND(13) RND(15) RND(26) RND(6)
    x0 = madd(x0, k0, one); x1 = madd(x1, k1 + 3u, one);
    RND(17) RND(29) RND(16) RND(24)
    x0 = madd(x0, k1, one); x1 = madd(x1, k2 + 4u, one);
    RND(13) RND(15) RND(26) RND(6)
    x1 = madd(x1, k0 + 5u, one);
#undef RND
    return x1;
}

// ---------------------------------------------------------------------------
// Main kernel. Grid: Tn*4 blocks x 256 threads. Block = (t, quadrant q).
// Thread (lane_hk = tid>>4, p = tid&15) handles hk_u = q*16 + lane_hk + 64u,
// u=0..3  =>  h = q + 4u (warp-uniform per iteration), k = lane_hk.
// Counter i = (h<<19) + (t<<8) + tid   (k*16+p == tid & 255).
// ---------------------------------------------------------------------------
__global__ __launch_bounds__(256) void main_kernel(
    const int* __restrict__ locations,
    const int* __restrict__ pos_idx,
    const float* __restrict__ norm,
    float* __restrict__ out)
{
    const int t   = blockIdx.x >> 2;
    const int q   = blockIdx.x & 3;
    const int tid = threadIdx.x;
    const int p   = tid & 15;

    __shared__ int   s_ori[TPn];
    __shared__ float s_norm;
    if (tid < TPn) {
        int pi = pos_idx[t];
        s_ori[tid] = locations[(size_t)pi * TPn + tid];
    }
    if (tid == 0) s_norm = norm[t];

    const uint32_t one = g_one;

    // prefetch inverse-permutation entries for this thread's 4 hk values
    const int base_hk = q * 16 + (tid >> 4);
    int jp_p[4], jp_m[4];
#pragma unroll
    for (int u = 0; u < 4; u++) {
        int hk = base_hk + 64 * u;
        jp_p[u] = c_jp.v[hk];          // +result column
        jp_m[u] = c_jp.v[hk + 257];    // -result column
    }

    __syncthreads();
    const int   c2  = s_ori[p];
    const float nrm = s_norm;
    float* outp = out + (size_t)t * (NCOL * TPn) + p;

    const uint32_t i0 = ((uint32_t)q << 19) + ((uint32_t)t << 8) + (uint32_t)tid;

#pragma unroll
    for (int u = 0; u < 4; u++) {
        const int h = q + 4 * u;
        int m;  // flip ^ mask, bits [0, h] only (bit h always set)
        if (h == 0) {
            m = 1;
        } else {
            uint32_t rb = tf_b(one, i0 + ((uint32_t)u << 21));
            m = (int)((rb & ((1u << h) - 1u)) | (1u << h));
        }
        const int res = c2 ^ m;                    // sign(res) == sign(c2)
        const int aa = (res < 0) ? -res : res;
        const int bb = (c2  < 0) ? -c2  : c2;
        const int e  = 32 - __clz((aa ^ bb) + 1);  // frexp exponent = bit length
        const float base = fmaf((float)e, -0.0625f, 1.0f);
        const float dp = base * nrm;               // sign product always +1
        const float dm = (res == 0) ? dp
                       : __int_as_float(__float_as_int(dp) ^ 0x80000000u);
        outp[(size_t)jp_p[u] * TPn] = dp;
        outp[(size_t)jp_m[u] * TPn] = dm;
    }

    if (q == 0 && tid < TPn) {  // ori column: d(ori,ori) = (1 - 1/16) * norm
        outp[(size_t)c_jp.v[256] * TPn] = 0.9375f * nrm;
    }
}

extern "C" void kernel_launch(void* const* d_in, const int* in_sizes, int n_in,
                              void* d_out, int out_size) {
    const int*   locations = (const int*)d_in[0];
    const int*   pos_idx   = (const int*)d_in[1];
    const float* norm      = (const float*)d_in[2];
    float*       out       = (float*)d_out;

    main_kernel<<<Tn * 4, 256>>>(locations, pos_idx, norm, out);
}